// round 1
// baseline (speedup 1.0000x reference)
#include <cuda_runtime.h>
#include <cstdint>

// Problem constants (shapes are fixed by the dataset)
#define M_TOT   8192      // 4 * 2048
#define K_IN    4096      // input features
#define RANK    256
#define N_OUT   4096
#define VERA_SCALE (32.0f / 256.0f)

// Rank-space intermediate t = (x @ A^T) * d_A   -> [M_TOT, RANK]
__device__ float g_t[(size_t)M_TOT * RANK];

// Classic NT SGEMM: Out[m][n] = (sum_k X[m][k] * W[n][k]) * colscale[n] * scale
// X: M x K row-major, W: N x K row-major. BM=BN=128, BK=16, 256 threads, 8x8/thread.
// Assumes M%128==0, N%128==0, K%16==0 (true for all three dims here).
template <int BM, int BN, int BK>
__global__ __launch_bounds__(256, 2)
void gemm_nt_scaled(const float* __restrict__ X,
                    const float* __restrict__ W,
                    const float* __restrict__ colscale,
                    float scale,
                    float* __restrict__ Out,
                    int M, int N, int K)
{
    __shared__ float As[BK][BM];   // transposed: As[k][m]
    __shared__ float Bs[BK][BN];   // transposed: Bs[k][n]

    const int bm = blockIdx.x * BM;
    const int bn = blockIdx.y * BN;
    const int tid = threadIdx.x;         // 0..255
    const int tx = tid & 15;             // 16 cols of threads
    const int ty = tid >> 4;             // 16 rows of threads

    float acc[8][8];
    #pragma unroll
    for (int i = 0; i < 8; ++i)
        #pragma unroll
        for (int j = 0; j < 8; ++j)
            acc[i][j] = 0.0f;

    const int KV = BK / 4;               // float4 chunks per row slab

    for (int k0 = 0; k0 < K; k0 += BK) {
        // Load X tile: BM rows x BK k's, vectorized along K, store transposed.
        #pragma unroll
        for (int i = 0; i < (BM * BK) / (256 * 4); ++i) {
            int idx = tid + i * 256;
            int row = idx / KV;
            int kc  = idx % KV;
            float4 v = *reinterpret_cast<const float4*>(
                X + (size_t)(bm + row) * K + k0 + kc * 4);
            As[kc * 4 + 0][row] = v.x;
            As[kc * 4 + 1][row] = v.y;
            As[kc * 4 + 2][row] = v.z;
            As[kc * 4 + 3][row] = v.w;
        }
        // Load W tile: BN rows x BK k's.
        #pragma unroll
        for (int i = 0; i < (BN * BK) / (256 * 4); ++i) {
            int idx = tid + i * 256;
            int row = idx / KV;
            int kc  = idx % KV;
            float4 v = *reinterpret_cast<const float4*>(
                W + (size_t)(bn + row) * K + k0 + kc * 4);
            Bs[kc * 4 + 0][row] = v.x;
            Bs[kc * 4 + 1][row] = v.y;
            Bs[kc * 4 + 2][row] = v.z;
            Bs[kc * 4 + 3][row] = v.w;
        }
        __syncthreads();

        #pragma unroll
        for (int kk = 0; kk < BK; ++kk) {
            float af[8], bf[8];
            // vector loads from smem
            *reinterpret_cast<float4*>(&af[0]) =
                *reinterpret_cast<const float4*>(&As[kk][ty * 8 + 0]);
            *reinterpret_cast<float4*>(&af[4]) =
                *reinterpret_cast<const float4*>(&As[kk][ty * 8 + 4]);
            *reinterpret_cast<float4*>(&bf[0]) =
                *reinterpret_cast<const float4*>(&Bs[kk][tx * 8 + 0]);
            *reinterpret_cast<float4*>(&bf[4]) =
                *reinterpret_cast<const float4*>(&Bs[kk][tx * 8 + 4]);
            #pragma unroll
            for (int i = 0; i < 8; ++i)
                #pragma unroll
                for (int j = 0; j < 8; ++j)
                    acc[i][j] = fmaf(af[i], bf[j], acc[i][j]);
        }
        __syncthreads();
    }

    // Epilogue: per-column scale (d_A or d_B) times uniform scale.
    float cs[8];
    #pragma unroll
    for (int j = 0; j < 8; ++j)
        cs[j] = colscale[bn + tx * 8 + j] * scale;

    #pragma unroll
    for (int i = 0; i < 8; ++i) {
        float* orow = Out + (size_t)(bm + ty * 8 + i) * N + bn + tx * 8;
        float4 o0, o1;
        o0.x = acc[i][0] * cs[0];
        o0.y = acc[i][1] * cs[1];
        o0.z = acc[i][2] * cs[2];
        o0.w = acc[i][3] * cs[3];
        o1.x = acc[i][4] * cs[4];
        o1.y = acc[i][5] * cs[5];
        o1.z = acc[i][6] * cs[6];
        o1.w = acc[i][7] * cs[7];
        *reinterpret_cast<float4*>(orow + 0) = o0;
        *reinterpret_cast<float4*>(orow + 4) = o1;
    }
}

extern "C" void kernel_launch(void* const* d_in, const int* in_sizes, int n_in,
                              void* d_out, int out_size)
{
    const float* x   = (const float*)d_in[0];  // (4,2048,4096) -> [8192][4096]
    const float* A   = (const float*)d_in[1];  // (256,4096)
    const float* B   = (const float*)d_in[2];  // (4096,256)
    const float* d_A = (const float*)d_in[3];  // (256,)
    const float* d_B = (const float*)d_in[4];  // (4096,)
    float* out = (float*)d_out;                // (4,2048,4096) -> [8192][4096]

    float* t = nullptr;
    cudaGetSymbolAddress((void**)&t, g_t);

    // GEMM1: t[m][r] = (sum_k x[m][k] * A[r][k]) * d_A[r]
    {
        dim3 grid(M_TOT / 128, RANK / 128);
        gemm_nt_scaled<128, 128, 16><<<grid, 256>>>(
            x, A, d_A, 1.0f, t, M_TOT, RANK, K_IN);
    }
    // GEMM2: out[m][o] = (sum_r t[m][r] * B[o][r]) * d_B[o] * SCALE
    {
        dim3 grid(M_TOT / 128, N_OUT / 128);
        gemm_nt_scaled<128, 128, 16><<<grid, 256>>>(
            t, B, d_B, VERA_SCALE, out, M_TOT, N_OUT, RANK);
    }
}

// round 3
// speedup vs baseline: 2.1444x; 2.1444x over previous
#include <cuda_runtime.h>
#include <cuda_bf16.h>
#include <cstdint>

#define M_TOT   8192
#define K_IN    4096
#define RANK    256
#define N_OUT   4096
#define VERA_SCALE (32.0f / 256.0f)

// rank-space intermediate t = (x @ A^T) * d_A : [M_TOT][RANK]
__device__ float g_t[(size_t)M_TOT * RANK];

// ------------- helpers -------------
__device__ __forceinline__ uint32_t smem_u32(const void* p) {
    uint32_t a;
    asm("{ .reg .u64 t; cvta.to.shared.u64 t, %1; cvt.u32.u64 %0, t; }" : "=r"(a) : "l"(p));
    return a;
}
__device__ __forceinline__ void ldsm4(uint32_t r[4], uint32_t addr) {
    asm volatile("ldmatrix.sync.aligned.m8n8.x4.shared.b16 {%0,%1,%2,%3}, [%4];"
                 : "=r"(r[0]), "=r"(r[1]), "=r"(r[2]), "=r"(r[3]) : "r"(addr));
}
__device__ __forceinline__ void mma_bf16(float c[4], const uint32_t a[4],
                                         uint32_t b0, uint32_t b1) {
    asm volatile(
        "mma.sync.aligned.m16n8k16.row.col.f32.bf16.bf16.f32 "
        "{%0,%1,%2,%3}, {%4,%5,%6,%7}, {%8,%9}, {%0,%1,%2,%3};"
        : "+f"(c[0]), "+f"(c[1]), "+f"(c[2]), "+f"(c[3])
        : "r"(a[0]), "r"(a[1]), "r"(a[2]), "r"(a[3]), "r"(b0), "r"(b1));
}
__device__ __forceinline__ uint32_t pk(__nv_bfloat16 a, __nv_bfloat16 b) {
    return (uint32_t)__bfloat16_as_ushort(a) | ((uint32_t)__bfloat16_as_ushort(b) << 16);
}
// SW128 swizzle on byte offset within a (rows x 128B) tile
__device__ __forceinline__ uint32_t sw128(uint32_t b) {
    return b ^ ((b >> 3) & 0x70);
}

// Load 128x64 fp32 tile (row stride ld) -> bf16 hi & lo SW128 tiles in smem.
__device__ __forceinline__ void load_cvt(const float* __restrict__ g, int ld,
                                         char* __restrict__ hi, char* __restrict__ lo,
                                         int tid) {
    #pragma unroll
    for (int it = 0; it < 8; ++it) {
        int idx = tid + it * 256;
        int row = idx >> 4;            // 16 float4 per 64-float row
        int c4  = (idx & 15) << 2;     // float index
        float4 v = *reinterpret_cast<const float4*>(g + (size_t)row * ld + c4);
        __nv_bfloat16 h0 = __float2bfloat16(v.x);
        __nv_bfloat16 h1 = __float2bfloat16(v.y);
        __nv_bfloat16 h2 = __float2bfloat16(v.z);
        __nv_bfloat16 h3 = __float2bfloat16(v.w);
        __nv_bfloat16 l0 = __float2bfloat16(v.x - __bfloat162float(h0));
        __nv_bfloat16 l1 = __float2bfloat16(v.y - __bfloat162float(h1));
        __nv_bfloat16 l2 = __float2bfloat16(v.z - __bfloat162float(h2));
        __nv_bfloat16 l3 = __float2bfloat16(v.w - __bfloat162float(h3));
        uint32_t off = sw128((uint32_t)(row * 128 + c4 * 2));
        uint2 hv; hv.x = pk(h0, h1); hv.y = pk(h2, h3);
        uint2 lv; lv.x = pk(l0, l1); lv.y = pk(l2, l3);
        *reinterpret_cast<uint2*>(hi + off) = hv;
        *reinterpret_cast<uint2*>(lo + off) = lv;
    }
}

// GEMM-NT: Out[m][n] = (sum_k X[m][k] * W[n][k]) * csc[n] * scale
// CTA tile 128x128, K-chunk 64, bf16x3 split precision on mma.sync tensor cores.
// 256 threads = 8 warps in a 4(m) x 2(n) grid; warp tile 32(m) x 64(n).
__global__ __launch_bounds__(256)
void vera_hmma(const float* __restrict__ X, const float* __restrict__ W,
               const float* __restrict__ csc, float scale, float* __restrict__ Out,
               int Ntot, int K)
{
    extern __shared__ char smem[];
    // layout: Xhi[16K] Xlo[16K] Whi[16K] Wlo[16K] cs[512B]
    char* sXhi = smem;
    char* sXlo = smem + 16384;
    char* sWhi = smem + 32768;
    char* sWlo = smem + 49152;
    float* cs  = reinterpret_cast<float*>(smem + 65536);
    const uint32_t sb = smem_u32(smem);

    const int tid = threadIdx.x;
    const int wid = tid >> 5;
    const int lid = tid & 31;
    const int warp_m = wid & 3;       // 4 warps along M
    const int warp_n = wid >> 2;      // 2 warps along N

    const int bm = blockIdx.x * 128;
    const int bn = blockIdx.y * 128;

    // per-column scales
    if (tid < 128) cs[tid] = csc[bn + tid] * scale;

    // ---- precompute per-lane ldmatrix offsets ----
    // A: lanes 0-15 -> rows mbase+0..15 (khalf 0), lanes 16-31 -> same rows khalf 1
    const int rowA = warp_m * 32 + (lid & 15);
    const uint32_t pA0 = (uint32_t)(rowA * 128);
    const uint32_t pA1 = pA0 + 16 * 128;
    const uint32_t kbA = (uint32_t)((lid >> 4) * 16);
    const uint32_t xA  = (uint32_t)((rowA & 7) << 4);
    // B: row = (l>>4)*8 + (l&7), khalf = (l>>3)&1
    const int rowB = warp_n * 64 + ((lid >> 4) * 8 + (lid & 7));
    const uint32_t pB0 = (uint32_t)(rowB * 128);
    const uint32_t kbB = (uint32_t)(((lid >> 3) & 1) * 16);
    const uint32_t xB  = (uint32_t)((rowB & 7) << 4);

    float acc[2][8][4];
    #pragma unroll
    for (int i = 0; i < 2; ++i)
        #pragma unroll
        for (int j = 0; j < 8; ++j)
            #pragma unroll
            for (int q = 0; q < 4; ++q)
                acc[i][j][q] = 0.0f;

    const int nchunks = K >> 6;
    const float* Xg = X + (size_t)bm * K;
    const float* Wg = W + (size_t)bn * K;

    for (int ch = 0; ch < nchunks; ++ch) {
        __syncthreads();   // previous compute done before overwriting smem
        load_cvt(Xg + ch * 64, K, sXhi, sXlo, tid);
        load_cvt(Wg + ch * 64, K, sWhi, sWlo, tid);
        __syncthreads();

        #pragma unroll
        for (int s = 0; s < 4; ++s) {
            const uint32_t aoff = ((uint32_t)(s * 32) + kbA) ^ xA;
            const uint32_t boff = ((uint32_t)(s * 32) + kbB) ^ xB;
            uint32_t ah0[4], ah1[4], al0[4], al1[4];
            ldsm4(ah0, sb + 0     + pA0 + aoff);
            ldsm4(ah1, sb + 0     + pA1 + aoff);
            ldsm4(al0, sb + 16384 + pA0 + aoff);
            ldsm4(al1, sb + 16384 + pA1 + aoff);
            #pragma unroll
            for (int np = 0; np < 4; ++np) {
                uint32_t bh[4], bl[4];
                ldsm4(bh, sb + 32768 + pB0 + (uint32_t)(np * 2048) + boff);
                ldsm4(bl, sb + 49152 + pB0 + (uint32_t)(np * 2048) + boff);
                // n-tile 2*np: regs {0,1}; n-tile 2*np+1: regs {2,3}
                mma_bf16(acc[0][2 * np],     ah0, bh[0], bh[1]);
                mma_bf16(acc[1][2 * np],     ah1, bh[0], bh[1]);
                mma_bf16(acc[0][2 * np + 1], ah0, bh[2], bh[3]);
                mma_bf16(acc[1][2 * np + 1], ah1, bh[2], bh[3]);
                // cross terms: hi*lo + lo*hi
                mma_bf16(acc[0][2 * np],     ah0, bl[0], bl[1]);
                mma_bf16(acc[1][2 * np],     ah1, bl[0], bl[1]);
                mma_bf16(acc[0][2 * np + 1], ah0, bl[2], bl[3]);
                mma_bf16(acc[1][2 * np + 1], ah1, bl[2], bl[3]);
                mma_bf16(acc[0][2 * np],     al0, bh[0], bh[1]);
                mma_bf16(acc[1][2 * np],     al1, bh[0], bh[1]);
                mma_bf16(acc[0][2 * np + 1], al0, bh[2], bh[3]);
                mma_bf16(acc[1][2 * np + 1], al1, bh[2], bh[3]);
            }
        }
    }

    // ---- epilogue: scale by csc[n]*scale, fp32 stores ----
    const int mrow0 = bm + warp_m * 32 + (lid >> 2);
    const int nc0   = warp_n * 64 + (lid & 3) * 2;
    #pragma unroll
    for (int mi = 0; mi < 2; ++mi) {
        #pragma unroll
        for (int nj = 0; nj < 8; ++nj) {
            const int n = nc0 + nj * 8;
            const float s0 = cs[n], s1 = cs[n + 1];
            float2 v0, v1;
            v0.x = acc[mi][nj][0] * s0; v0.y = acc[mi][nj][1] * s1;
            v1.x = acc[mi][nj][2] * s0; v1.y = acc[mi][nj][3] * s1;
            const int m0 = mrow0 + mi * 16;
            *reinterpret_cast<float2*>(Out + (size_t)m0 * Ntot + bn + n) = v0;
            *reinterpret_cast<float2*>(Out + (size_t)(m0 + 8) * Ntot + bn + n) = v1;
        }
    }
}

extern "C" void kernel_launch(void* const* d_in, const int* in_sizes, int n_in,
                              void* d_out, int out_size)
{
    const float* x   = (const float*)d_in[0];  // [8192][4096]
    const float* A   = (const float*)d_in[1];  // [256][4096]
    const float* B   = (const float*)d_in[2];  // [4096][256]
    const float* d_A = (const float*)d_in[3];  // [256]
    const float* d_B = (const float*)d_in[4];  // [4096]
    float* out = (float*)d_out;                // [8192][4096]

    float* t = nullptr;
    cudaGetSymbolAddress((void**)&t, g_t);

    constexpr int SMEM = 65536 + 512;
    cudaFuncSetAttribute(vera_hmma, cudaFuncAttributeMaxDynamicSharedMemorySize, SMEM);

    // GEMM1: t = (x @ A^T) * d_A      M=8192, N=256, K=4096
    {
        dim3 grid(M_TOT / 128, RANK / 128);   // 64 x 2
        vera_hmma<<<grid, 256, SMEM>>>(x, A, d_A, 1.0f, t, RANK, K_IN);
    }
    // GEMM2: out = (t @ B^T) * d_B * SCALE   M=8192, N=4096, K=256
    {
        dim3 grid(M_TOT / 128, N_OUT / 128);  // 64 x 32
        vera_hmma<<<grid, 256, SMEM>>>(t, B, d_B, VERA_SCALE, out, N_OUT, RANK);
    }
}